// round 8
// baseline (speedup 1.0000x reference)
#include <cuda_runtime.h>
#include <cstdint>

// Conv2d: x(32,128,112,112) fp32, w(256,128,3,3), stride 2, VALID -> out(32,256,55,55)
// Implicit GEMM, mma.sync m16n8k8 tf32. CTA tile 128x256, 3-stage cp.async pipeline.
// Prepass: x -> NHWC tf32 (g_xs), w -> (cout)(kh,kw,cin) tf32 (g_ws). K order is
// (kh,kw,cin) so every BK=32 chunk of an A row is one contiguous 128B segment.

#define B_    32
#define CIN   128
#define HIN   112
#define WIN   112
#define COUT  256
#define OHW   55
#define OHW2  (OHW*OHW)          // 3025
#define KTOT  1152
#define M_TOT (B_*OHW2)          // 96800
#define CHW   (CIN*HIN*WIN)
#define XTOT  (B_*CHW)           // 51380224
#define WTOT  (COUT*KTOT)        // 294912

#define BM 128
#define BN 256
#define BK 32
#define NCHUNK (KTOT/BK)         // 36
#define NSTAGE 3
#define SLD 36                   // smem row stride in floats (pad 4)

#define ASTAGE (128*SLD)         // 4608 floats
#define BSTAGE (256*SLD)         // 9216 floats
#define OFF_B   (NSTAGE*ASTAGE)             // 13824
#define SMEM_FLOATS (OFF_B + NSTAGE*BSTAGE) // 41472
#define SMEM_BYTES  (SMEM_FLOATS*4)         // 165888

__device__ float g_xs[XTOT];   // NHWC: [b][h][w][c]
__device__ float g_ws[WTOT];   // [cout][(kh*3+kw)*128 + cin]

__device__ __forceinline__ float f2tf32f(float f) {
    uint32_t r;
    asm("cvt.rna.tf32.f32 %0, %1;" : "=r"(r) : "f"(f));
    return __uint_as_float(r);
}

// ---- prepass: NCHW -> NHWC transpose + tf32 round. One block per (b,h). ----
__global__ void __launch_bounds__(256)
cvt_x_nhwc(const float* __restrict__ x) {
    __shared__ float tile[128 * 113];
    const int bh  = blockIdx.x;              // b*112 + h
    const int tid = threadIdx.x;
    const long xbase = (long)(bh / HIN) * CHW + (long)(bh % HIN) * WIN;

    for (int idx = tid; idx < CIN * WIN; idx += 256) {
        int c = idx / WIN, w = idx - c * WIN;
        tile[c * 113 + w] = f2tf32f(x[xbase + (long)c * (HIN * WIN) + w]);
    }
    __syncthreads();
    const long obase = (long)bh * (WIN * CIN);
    for (int o = tid; o < WIN * CIN; o += 256) {
        int w = o >> 7, c = o & 127;
        g_xs[obase + o] = tile[c * 113 + w];
    }
}

__global__ void __launch_bounds__(256)
cvt_w_kernel(const float* __restrict__ w) {
    int i = blockIdx.x * 256 + threadIdx.x;
    if (i >= WTOT) return;
    int cout = i / KTOT, r = i - cout * KTOT;
    int t = r >> 7, cin = r & 127;           // t = kh*3+kw
    g_ws[i] = f2tf32f(w[cout * KTOT + cin * 9 + t]);
}

__device__ __forceinline__ uint32_t smem_u32(const void* p) {
    uint32_t a;
    asm("{ .reg .u64 t; cvta.to.shared.u64 t, %1; cvt.u32.u64 %0, t; }" : "=r"(a) : "l"(p));
    return a;
}
__device__ __forceinline__ void cp16(uint32_t d, const float* s) {
    asm volatile("cp.async.cg.shared.global [%0], [%1], 16;"
                 :: "r"(d), "l"(__cvta_generic_to_global(s)) : "memory");
}
__device__ __forceinline__ void cp_commit() {
    asm volatile("cp.async.commit_group;" ::: "memory");
}
__device__ __forceinline__ void cp_wait2() {
    asm volatile("cp.async.wait_group 2;" ::: "memory");
}
__device__ __forceinline__ void mma_tf32(float d[4],
                                         uint32_t a0, uint32_t a1, uint32_t a2, uint32_t a3,
                                         uint32_t b0, uint32_t b1) {
    asm volatile(
        "mma.sync.aligned.m16n8k8.row.col.f32.tf32.tf32.f32 "
        "{%0,%1,%2,%3}, {%4,%5,%6,%7}, {%8,%9}, {%0,%1,%2,%3};"
        : "+f"(d[0]), "+f"(d[1]), "+f"(d[2]), "+f"(d[3])
        : "r"(a0), "r"(a1), "r"(a2), "r"(a3), "r"(b0), "r"(b1));
}

__global__ void __launch_bounds__(256)
conv_mma_kernel(float* __restrict__ out) {
    extern __shared__ float smem[];

    const int tid  = threadIdx.x;
    const int wid  = tid >> 5;
    const int lane = tid & 31;
    const int m0   = blockIdx.x * BM;

    // producer mapping: kk = 4-float group (0..7), rsel = row selector (0..31)
    const int kk   = tid & 7;
    const int rsel = tid >> 3;

    // A row bases in NHWC: b*CHW + (2oh*112 + 2ow)*128
    int abase[4];
    #pragma unroll
    for (int j = 0; j < 4; j++) {
        int m = m0 + j * 32 + rsel;
        int mm  = (m < M_TOT) ? m : 0;
        int b   = mm / OHW2;
        int rem = mm - b * OHW2;
        int oh  = rem / OHW;
        int ow  = rem - oh * OHW;
        abase[j] = b * CHW + ((2 * oh) * WIN + 2 * ow) * CIN;
    }

    const uint32_t sb = smem_u32(smem);

    // ---- issue loads for chunk c into stage s ----
    auto issue = [&](int c, int s) {
        const int t    = c >> 2;             // kh*3+kw
        const int cin0 = (c & 3) * 32;
        const int kh   = t / 3;
        const int kw   = t - kh * 3;
        const int hw   = (kh * WIN + kw) * CIN + cin0 + kk * 4;

        const uint32_t Ab = sb + (s * ASTAGE) * 4;
        #pragma unroll
        for (int j = 0; j < 4; j++) {
            const int row = j * 32 + rsel;
            cp16(Ab + (row * SLD + kk * 4) * 4, g_xs + abase[j] + hw);
        }
        const int k0 = c * BK;
        const uint32_t Bb = sb + (OFF_B + s * BSTAGE) * 4;
        #pragma unroll
        for (int j = 0; j < 8; j++) {
            const int row = j * 32 + rsel;
            cp16(Bb + (row * SLD + kk * 4) * 4, g_ws + (long)row * KTOT + k0 + kk * 4);
        }
    };

    // ---- compute mapping: 8 warps = 2(M) x 4(N), warp tile 64x64 ----
    const int wm = wid & 1;
    const int wn = wid >> 1;
    const int lr = lane >> 2;      // 0..7
    const int lc = lane & 3;       // 0..3

    float d[4][8][4];
    #pragma unroll
    for (int a = 0; a < 4; a++)
        #pragma unroll
        for (int b = 0; b < 8; b++)
            #pragma unroll
            for (int c = 0; c < 4; c++) d[a][b][c] = 0.0f;

    issue(0, 0); cp_commit();
    issue(1, 1); cp_commit();

    for (int i = 0; i < NCHUNK; i++) {
        const int c = i + 2;
        if (c < NCHUNK) issue(c, c % NSTAGE);
        cp_commit();
        cp_wait2();
        __syncthreads();

        const int st = i % NSTAGE;
        const float* A  = smem + st * ASTAGE + wm * 64 * SLD;
        const float* Bs = smem + OFF_B + st * BSTAGE + wn * 64 * SLD;

        #pragma unroll
        for (int ks = 0; ks < 4; ks++) {
            const int cb = ks * 8 + lc * 2;
            float2 aLo[4], aHi[4], bF[8];
            #pragma unroll
            for (int tm = 0; tm < 4; tm++) {
                aLo[tm] = *(const float2*)&A[(tm * 16 + lr) * SLD + cb];
                aHi[tm] = *(const float2*)&A[(tm * 16 + lr + 8) * SLD + cb];
            }
            #pragma unroll
            for (int tn = 0; tn < 8; tn++)
                bF[tn] = *(const float2*)&Bs[(tn * 8 + lr) * SLD + cb];
            #pragma unroll
            for (int tm = 0; tm < 4; tm++) {
                const uint32_t a0 = __float_as_uint(aLo[tm].x);
                const uint32_t a1 = __float_as_uint(aHi[tm].x);
                const uint32_t a2 = __float_as_uint(aLo[tm].y);
                const uint32_t a3 = __float_as_uint(aHi[tm].y);
                #pragma unroll
                for (int tn = 0; tn < 8; tn++)
                    mma_tf32(d[tm][tn], a0, a1, a2, a3,
                             __float_as_uint(bF[tn].x), __float_as_uint(bF[tn].y));
            }
        }
        __syncthreads();
    }

    // ---- epilogue: scatter to NCHW output ----
    const int nbase = wn * 64;
    #pragma unroll
    for (int tm = 0; tm < 4; tm++) {
        #pragma unroll
        for (int h = 0; h < 2; h++) {
            const int m = m0 + wm * 64 + tm * 16 + h * 8 + lr;
            if (m >= M_TOT) continue;
            int b   = m / OHW2;
            int rem = m - b * OHW2;
            int oh  = rem / OHW;
            int ow  = rem - oh * OHW;
            const long obase = ((long)b * COUT + nbase) * OHW2 + oh * OHW + ow;
            #pragma unroll
            for (int tn = 0; tn < 8; tn++) {
                const int n_off = tn * 8 + lc * 2;
                out[obase + (long)n_off * OHW2]       = d[tm][tn][h * 2 + 0];
                out[obase + (long)(n_off + 1) * OHW2] = d[tm][tn][h * 2 + 1];
            }
        }
    }
}

extern "C" void kernel_launch(void* const* d_in, const int* in_sizes, int n_in,
                              void* d_out, int out_size) {
    const float* x = (const float*)d_in[0];
    const float* w = (const float*)d_in[1];
    float* out = (float*)d_out;

    cvt_x_nhwc<<<B_ * HIN, 256>>>(x);                 // 3584 blocks
    cvt_w_kernel<<<(WTOT + 255) / 256, 256>>>(w);

    cudaFuncSetAttribute(conv_mma_kernel,
                         cudaFuncAttributeMaxDynamicSharedMemorySize, SMEM_BYTES);

    dim3 grid((M_TOT + BM - 1) / BM, 1);   // 757
    conv_mma_kernel<<<grid, 256, SMEM_BYTES>>>(out);
}

// round 11
// speedup vs baseline: 1.2070x; 1.2070x over previous
#include <cuda_runtime.h>
#include <cstdint>

// Conv2d: x(32,128,112,112) fp32, w(256,128,3,3), stride 2, VALID -> out(32,256,55,55)
// Implicit GEMM, mma.sync m16n8k8 tf32.
// CTA tile 128x128, 128 threads (4 warps, 2x2 of 64x64), 3-stage cp.async pipeline,
// smem 110.6KB/CTA -> 2 CTAs/SM for cross-CTA overlap.

#define B_    32
#define CIN   128
#define HIN   112
#define WIN   112
#define COUT  256
#define OHW   55
#define OHW2  (OHW*OHW)          // 3025
#define KTOT  1152
#define M_TOT (B_*OHW2)          // 96800
#define CHW   (CIN*HIN*WIN)
#define XTOT  (B_*CHW)           // 51380224
#define WTOT  (COUT*KTOT)        // 294912

#define BM 128
#define BN 128
#define BK 32
#define NCHUNK (KTOT/BK)         // 36
#define NSTAGE 3
#define SLD 36                   // smem row stride in floats (pad 4)

#define ASTG (128*SLD)                   // 4608 floats
#define STG  (2*ASTG)                    // A+B per stage = 9216 floats
#define SMEM_BYTES (NSTAGE*STG*4)        // 110592 B

__device__ float g_xs[XTOT];   // tf32-rounded x, NCHW
__device__ float g_ws[WTOT];   // tf32-rounded w, [cout][cin*9 + kh*3 + kw]
__device__ int   g_off[KTOT];  // im2col: off[k] = cin*HW + kh*W + kw

__device__ __forceinline__ float f2tf32f(float f) {
    uint32_t r;
    asm("cvt.rna.tf32.f32 %0, %1;" : "=r"(r) : "f"(f));
    return __uint_as_float(r);
}

__global__ void __launch_bounds__(256)
cvt_x_kernel(const float* __restrict__ x) {
    long i = ((long)blockIdx.x * 256 + threadIdx.x) * 4;
    if (i >= XTOT) return;
    float4 v = *(const float4*)(x + i);
    v.x = f2tf32f(v.x); v.y = f2tf32f(v.y); v.z = f2tf32f(v.z); v.w = f2tf32f(v.w);
    *(float4*)(g_xs + i) = v;
}

__global__ void __launch_bounds__(256)
cvt_w_kernel(const float* __restrict__ w) {
    long i = (long)blockIdx.x * 256 + threadIdx.x;
    if (i < KTOT) {
        int k = (int)i;
        int cin = k / 9, r = k - cin * 9;
        int kh = r / 3, kw = r - kh * 3;
        g_off[k] = cin * (HIN * WIN) + kh * WIN + kw;
    }
    i *= 4;
    if (i >= WTOT) return;
    float4 v = *(const float4*)(w + i);
    v.x = f2tf32f(v.x); v.y = f2tf32f(v.y); v.z = f2tf32f(v.z); v.w = f2tf32f(v.w);
    *(float4*)(g_ws + i) = v;
}

__device__ __forceinline__ uint32_t smem_u32(const void* p) {
    uint32_t a;
    asm("{ .reg .u64 t; cvta.to.shared.u64 t, %1; cvt.u32.u64 %0, t; }" : "=r"(a) : "l"(p));
    return a;
}
__device__ __forceinline__ void cp4(uint32_t d, const float* s) {
    asm volatile("cp.async.ca.shared.global [%0], [%1], 4;"
                 :: "r"(d), "l"(__cvta_generic_to_global(s)) : "memory");
}
__device__ __forceinline__ void cp16(uint32_t d, const float* s) {
    asm volatile("cp.async.cg.shared.global [%0], [%1], 16;"
                 :: "r"(d), "l"(__cvta_generic_to_global(s)) : "memory");
}
__device__ __forceinline__ void cp_commit() {
    asm volatile("cp.async.commit_group;" ::: "memory");
}
__device__ __forceinline__ void cp_wait2() {
    asm volatile("cp.async.wait_group 2;" ::: "memory");
}
__device__ __forceinline__ void mma_tf32(float d[4],
                                         uint32_t a0, uint32_t a1, uint32_t a2, uint32_t a3,
                                         uint32_t b0, uint32_t b1) {
    asm volatile(
        "mma.sync.aligned.m16n8k8.row.col.f32.tf32.tf32.f32 "
        "{%0,%1,%2,%3}, {%4,%5,%6,%7}, {%8,%9}, {%0,%1,%2,%3};"
        : "+f"(d[0]), "+f"(d[1]), "+f"(d[2]), "+f"(d[3])
        : "r"(a0), "r"(a1), "r"(a2), "r"(a3), "r"(b0), "r"(b1));
}

__global__ void __launch_bounds__(128, 2)
conv_mma_kernel(float* __restrict__ out) {
    extern __shared__ float smem[];

    const int tid  = threadIdx.x;
    const int wid  = tid >> 5;
    const int lane = tid & 31;
    const int m0   = blockIdx.x * BM;
    const int n0   = blockIdx.y * BN;

    // producer mapping: kk = 4-float K group (0..7), rsel = row selector (0..15)
    const int kk   = tid & 7;
    const int rsel = tid >> 3;

    // A row bases (clamped for OOB m; results masked in epilogue)
    int abase[8];
    #pragma unroll
    for (int j = 0; j < 8; j++) {
        int m = m0 + j * 16 + rsel;
        int mm  = (m < M_TOT) ? m : 0;
        int b   = mm / OHW2;
        int rem = mm - b * OHW2;
        int oh  = rem / OHW;
        int ow  = rem - oh * OHW;
        abase[j] = b * CHW + (2 * oh) * WIN + 2 * ow;
    }

    const uint32_t sb = smem_u32(smem);

    auto issue = [&](int c, int s) {
        const int k0 = c * BK;
        const int4 ko = *(const int4*)(g_off + k0 + kk * 4);
        const uint32_t Ab = sb + (s * STG) * 4;
        #pragma unroll
        for (int j = 0; j < 8; j++) {
            const int row = j * 16 + rsel;
            const uint32_t da = Ab + (row * SLD + kk * 4) * 4;
            cp4(da,      g_xs + abase[j] + ko.x);
            cp4(da + 4,  g_xs + abase[j] + ko.y);
            cp4(da + 8,  g_xs + abase[j] + ko.z);
            cp4(da + 12, g_xs + abase[j] + ko.w);
        }
        const uint32_t Bb = sb + (s * STG + ASTG) * 4;
        #pragma unroll
        for (int j = 0; j < 8; j++) {
            const int row = j * 16 + rsel;
            cp16(Bb + (row * SLD + kk * 4) * 4,
                 g_ws + (long)(n0 + row) * KTOT + k0 + kk * 4);
        }
    };

    // compute mapping: 4 warps = 2(M) x 2(N), warp tile 64x64
    const int wm = wid & 1;
    const int wn = wid >> 1;
    const int lr = lane >> 2;      // 0..7
    const int lc = lane & 3;       // 0..3

    float d[4][8][4];
    #pragma unroll
    for (int a = 0; a < 4; a++)
        #pragma unroll
        for (int b = 0; b < 8; b++)
            #pragma unroll
            for (int c = 0; c < 4; c++) d[a][b][c] = 0.0f;

    issue(0, 0); cp_commit();
    issue(1, 1); cp_commit();

    for (int i = 0; i < NCHUNK; i++) {
        const int c = i + 2;
        if (c < NCHUNK) issue(c, c % NSTAGE);
        cp_commit();
        cp_wait2();
        __syncthreads();

        const int st = i % NSTAGE;
        const float* A  = smem + st * STG + wm * 64 * SLD;
        const float* Bs = smem + st * STG + ASTG + wn * 64 * SLD;

        #pragma unroll
        for (int ks = 0; ks < 4; ks++) {
            const int cb = ks * 8 + lc * 2;
            float2 aLo[4], aHi[4], bF[8];
            #pragma unroll
            for (int tm = 0; tm < 4; tm++) {
                aLo[tm] = *(const float2*)&A[(tm * 16 + lr) * SLD + cb];
                aHi[tm] = *(const float2*)&A[(tm * 16 + lr + 8) * SLD + cb];
            }
            #pragma unroll
            for (int tn = 0; tn < 8; tn++)
                bF[tn] = *(const float2*)&Bs[(tn * 8 + lr) * SLD + cb];
            #pragma unroll
            for (int tm = 0; tm < 4; tm++) {
                const uint32_t a0 = __float_as_uint(aLo[tm].x);
                const uint32_t a1 = __float_as_uint(aHi[tm].x);
                const uint32_t a2 = __float_as_uint(aLo[tm].y);
                const uint32_t a3 = __float_as_uint(aHi[tm].y);
                #pragma unroll
                for (int tn = 0; tn < 8; tn++)
                    mma_tf32(d[tm][tn], a0, a1, a2, a3,
                             __float_as_uint(bF[tn].x), __float_as_uint(bF[tn].y));
            }
        }
        __syncthreads();
    }

    // epilogue: scatter to NCHW output
    const int nbase = n0 + wn * 64;
    #pragma unroll
    for (int tm = 0; tm < 4; tm++) {
        #pragma unroll
        for (int h = 0; h < 2; h++) {
            const int m = m0 + wm * 64 + tm * 16 + h * 8 + lr;
            if (m >= M_TOT) continue;
            int b   = m / OHW2;
            int rem = m - b * OHW2;
            int oh  = rem / OHW;
            int ow  = rem - oh * OHW;
            const long obase = ((long)b * COUT + nbase) * OHW2 + oh * OHW + ow;
            #pragma unroll
            for (int tn = 0; tn < 8; tn++) {
                const int n_off = tn * 8 + lc * 2;
                out[obase + (long)n_off * OHW2]       = d[tm][tn][h * 2 + 0];
                out[obase + (long)(n_off + 1) * OHW2] = d[tm][tn][h * 2 + 1];
            }
        }
    }
}

extern "C" void kernel_launch(void* const* d_in, const int* in_sizes, int n_in,
                              void* d_out, int out_size) {
    const float* x = (const float*)d_in[0];
    const float* w = (const float*)d_in[1];
    float* out = (float*)d_out;

    cvt_x_kernel<<<(XTOT / 4 + 255) / 256, 256>>>(x);
    cvt_w_kernel<<<(WTOT / 4 + 255) / 256, 256>>>(w);

    cudaFuncSetAttribute(conv_mma_kernel,
                         cudaFuncAttributeMaxDynamicSharedMemorySize, SMEM_BYTES);

    dim3 grid((M_TOT + BM - 1) / BM, COUT / BN);   // (757, 2)
    conv_mma_kernel<<<grid, 128, SMEM_BYTES>>>(out);
}

// round 12
// speedup vs baseline: 1.3519x; 1.1200x over previous
#include <cuda_runtime.h>
#include <cstdint>

// Conv2d: x(32,128,112,112) fp32, w(256,128,3,3), stride 2, VALID -> out(32,256,55,55)
// Implicit GEMM, mma.sync m16n8k8 tf32. CTA tile 128x256, 3-stage cp.async pipeline.
// A-gather lanes run along M (coalesced stride-2, 50% sector eff) instead of along K
// (scattered, 12.5%). Prepasses round x/w to tf32 (rna) into __device__ scratch.

#define B_    32
#define CIN   128
#define HIN   112
#define WIN   112
#define COUT  256
#define OHW   55
#define OHW2  (OHW*OHW)          // 3025
#define KTOT  1152
#define M_TOT (B_*OHW2)          // 96800
#define CHW   (CIN*HIN*WIN)
#define XTOT  (B_*CHW)           // 51380224
#define WTOT  (COUT*KTOT)        // 294912

#define BM 128
#define BN 256
#define BK 32
#define NCHUNK (KTOT/BK)         // 36
#define NSTAGE 3
#define SLD 36                   // smem row stride in floats (pad 4)

#define ASTAGE (128*SLD)         // 4608 floats
#define BSTAGE (256*SLD)         // 9216 floats
#define OFF_B   (NSTAGE*ASTAGE)             // 13824
#define SMEM_FLOATS (OFF_B + NSTAGE*BSTAGE) // 41472
#define SMEM_BYTES  (SMEM_FLOATS*4)         // 165888

__device__ float g_xs[XTOT];   // tf32-rounded x, NCHW
__device__ float g_ws[WTOT];   // tf32-rounded w
__device__ int   g_off[KTOT];  // im2col: off[k] = cin*HW + kh*W + kw

__device__ __forceinline__ float f2tf32f(float f) {
    uint32_t r;
    asm("cvt.rna.tf32.f32 %0, %1;" : "=r"(r) : "f"(f));
    return __uint_as_float(r);
}

__global__ void __launch_bounds__(256)
cvt_x_kernel(const float* __restrict__ x) {
    long i = ((long)blockIdx.x * 256 + threadIdx.x) * 4;
    if (i >= XTOT) return;
    float4 v = *(const float4*)(x + i);
    v.x = f2tf32f(v.x); v.y = f2tf32f(v.y); v.z = f2tf32f(v.z); v.w = f2tf32f(v.w);
    *(float4*)(g_xs + i) = v;
}

__global__ void __launch_bounds__(256)
cvt_w_kernel(const float* __restrict__ w) {
    long i = (long)blockIdx.x * 256 + threadIdx.x;
    if (i < KTOT) {
        int k = (int)i;
        int cin = k / 9, r = k - cin * 9;
        int kh = r / 3, kw = r - kh * 3;
        g_off[k] = cin * (HIN * WIN) + kh * WIN + kw;
    }
    i *= 4;
    if (i >= WTOT) return;
    float4 v = *(const float4*)(w + i);
    v.x = f2tf32f(v.x); v.y = f2tf32f(v.y); v.z = f2tf32f(v.z); v.w = f2tf32f(v.w);
    *(float4*)(g_ws + i) = v;
}

__device__ __forceinline__ uint32_t smem_u32(const void* p) {
    uint32_t a;
    asm("{ .reg .u64 t; cvta.to.shared.u64 t, %1; cvt.u32.u64 %0, t; }" : "=r"(a) : "l"(p));
    return a;
}
__device__ __forceinline__ void cp4(uint32_t d, const float* s) {
    asm volatile("cp.async.ca.shared.global [%0], [%1], 4;"
                 :: "r"(d), "l"(__cvta_generic_to_global(s)) : "memory");
}
__device__ __forceinline__ void cp16(uint32_t d, const float* s) {
    asm volatile("cp.async.cg.shared.global [%0], [%1], 16;"
                 :: "r"(d), "l"(__cvta_generic_to_global(s)) : "memory");
}
__device__ __forceinline__ void cp_commit() {
    asm volatile("cp.async.commit_group;" ::: "memory");
}
__device__ __forceinline__ void cp_wait2() {
    asm volatile("cp.async.wait_group 2;" ::: "memory");
}
__device__ __forceinline__ void mma_tf32(float d[4],
                                         uint32_t a0, uint32_t a1, uint32_t a2, uint32_t a3,
                                         uint32_t b0, uint32_t b1) {
    asm volatile(
        "mma.sync.aligned.m16n8k8.row.col.f32.tf32.tf32.f32 "
        "{%0,%1,%2,%3}, {%4,%5,%6,%7}, {%8,%9}, {%0,%1,%2,%3};"
        : "+f"(d[0]), "+f"(d[1]), "+f"(d[2]), "+f"(d[3])
        : "r"(a0), "r"(a1), "r"(a2), "r"(a3), "r"(b0), "r"(b1));
}

__global__ void __launch_bounds__(256)
conv_mma_kernel(float* __restrict__ out) {
    extern __shared__ float smem[];

    const int tid  = threadIdx.x;
    const int wid  = tid >> 5;
    const int lane = tid & 31;
    const int m0   = blockIdx.x * BM;

    // ---- A producer: warp = k-group (4 k cols), lane = m within 32-row group ----
    // (lanes along M -> one cp4 instruction spans 256B contiguous in x: 8 sectors)
    int abase[4];
    #pragma unroll
    for (int j = 0; j < 4; j++) {
        int m = m0 + j * 32 + lane;
        int mm  = (m < M_TOT) ? m : 0;
        int b   = mm / OHW2;
        int rem = mm - b * OHW2;
        int oh  = rem / OHW;
        int ow  = rem - oh * OHW;
        abase[j] = b * CHW + (2 * oh) * WIN + 2 * ow;
    }

    // ---- B producer mapping (k-major lanes: 4 rows x 128B contiguous / instr) ----
    const int kkB = tid & 7;
    const int rB  = tid >> 3;    // 0..31

    const uint32_t sb = smem_u32(smem);

    auto issue = [&](int c, int s) {
        const int k0 = c * BK;
        // A: this warp owns k cols wid*4 .. wid*4+3
        const int4 ko = *(const int4*)(g_off + k0 + wid * 4);
        const uint32_t Ab = sb + (s * ASTAGE) * 4;
        #pragma unroll
        for (int j = 0; j < 4; j++) {
            const int row = j * 32 + lane;
            const uint32_t da = Ab + (row * SLD + wid * 4) * 4;
            cp4(da,      g_xs + abase[j] + ko.x);
            cp4(da + 4,  g_xs + abase[j] + ko.y);
            cp4(da + 8,  g_xs + abase[j] + ko.z);
            cp4(da + 12, g_xs + abase[j] + ko.w);
        }
        // B: 256 rows x 32 k
        const uint32_t Bb = sb + (OFF_B + s * BSTAGE) * 4;
        #pragma unroll
        for (int j = 0; j < 8; j++) {
            const int row = j * 32 + rB;
            cp16(Bb + (row * SLD + kkB * 4) * 4,
                 g_ws + (long)row * KTOT + k0 + kkB * 4);
        }
    };

    // ---- compute mapping: 8 warps = 2(M) x 4(N), warp tile 64x64 ----
    const int wm = wid & 1;
    const int wn = wid >> 1;
    const int lr = lane >> 2;      // 0..7
    const int lc = lane & 3;       // 0..3

    float d[4][8][4];
    #pragma unroll
    for (int a = 0; a < 4; a++)
        #pragma unroll
        for (int b = 0; b < 8; b++)
            #pragma unroll
            for (int c = 0; c < 4; c++) d[a][b][c] = 0.0f;

    issue(0, 0); cp_commit();
    issue(1, 1); cp_commit();

    for (int i = 0; i < NCHUNK; i++) {
        const int c = i + 2;
        if (c < NCHUNK) issue(c, c % NSTAGE);
        cp_commit();
        cp_wait2();
        __syncthreads();

        const int st = i % NSTAGE;
        const float* A  = smem + st * ASTAGE + wm * 64 * SLD;
        const float* Bs = smem + OFF_B + st * BSTAGE + wn * 64 * SLD;

        #pragma unroll
        for (int ks = 0; ks < 4; ks++) {
            const int cb = ks * 8 + lc * 2;
            float2 aLo[4], aHi[4], bF[8];
            #pragma unroll
            for (int tm = 0; tm < 4; tm++) {
                aLo[tm] = *(const float2*)&A[(tm * 16 + lr) * SLD + cb];
                aHi[tm] = *(const float2*)&A[(tm * 16 + lr + 8) * SLD + cb];
            }
            #pragma unroll
            for (int tn = 0; tn < 8; tn++)
                bF[tn] = *(const float2*)&Bs[(tn * 8 + lr) * SLD + cb];
            #pragma unroll
            for (int tm = 0; tm < 4; tm++) {
                const uint32_t a0 = __float_as_uint(aLo[tm].x);
                const uint32_t a1 = __float_as_uint(aHi[tm].x);
                const uint32_t a2 = __float_as_uint(aLo[tm].y);
                const uint32_t a3 = __float_as_uint(aHi[tm].y);
                #pragma unroll
                for (int tn = 0; tn < 8; tn++)
                    mma_tf32(d[tm][tn], a0, a1, a2, a3,
                             __float_as_uint(bF[tn].x), __float_as_uint(bF[tn].y));
            }
        }
        __syncthreads();
    }

    // ---- epilogue: scatter to NCHW output ----
    const int nbase = wn * 64;
    #pragma unroll
    for (int tm = 0; tm < 4; tm++) {
        #pragma unroll
        for (int h = 0; h < 2; h++) {
            const int m = m0 + wm * 64 + tm * 16 + h * 8 + lr;
            if (m >= M_TOT) continue;
            int b   = m / OHW2;
            int rem = m - b * OHW2;
            int oh  = rem / OHW;
            int ow  = rem - oh * OHW;
            const long obase = ((long)b * COUT + nbase) * OHW2 + oh * OHW + ow;
            #pragma unroll
            for (int tn = 0; tn < 8; tn++) {
                const int n_off = tn * 8 + lc * 2;
                out[obase + (long)n_off * OHW2]       = d[tm][tn][h * 2 + 0];
                out[obase + (long)(n_off + 1) * OHW2] = d[tm][tn][h * 2 + 1];
            }
        }
    }
}

extern "C" void kernel_launch(void* const* d_in, const int* in_sizes, int n_in,
                              void* d_out, int out_size) {
    const float* x = (const float*)d_in[0];
    const float* w = (const float*)d_in[1];
    float* out = (float*)d_out;

    cvt_x_kernel<<<(XTOT / 4 + 255) / 256, 256>>>(x);
    cvt_w_kernel<<<(WTOT / 4 + 255) / 256, 256>>>(w);

    cudaFuncSetAttribute(conv_mma_kernel,
                         cudaFuncAttributeMaxDynamicSharedMemorySize, SMEM_BYTES);

    dim3 grid((M_TOT + BM - 1) / BM, 1);   // 757
    conv_mma_kernel<<<grid, 256, SMEM_BYTES>>>(out);
}